// round 6
// baseline (speedup 1.0000x reference)
#include <cuda_runtime.h>
#include <cstdint>
#include <cstddef>

// ----------------------------------------------------------------------------
// Round 4: split the x-contribution out of the recurrence.
//   preact(t) = x_t@W1x  (parallel over all t -> prolog GEMM kernel)
//             + a(t)@W1a (sequential)
//   a <- a + W2^T tanh(preact + b1) + b2
// Prolog: pre[m][j] = x[m,:]@W1x, m = b*T+t, 8192 CTAs, FFMA2-saturating.
// Main:   persistent 32 clusters x 4 CTAs, hidden 4-way split, fp32 W1a/W2
//         resident in smem, 8-way K-split GEMMs (dup=1), single-round 8-buffer
//         partial combine, 4 syncthreads + 1 cluster barrier per step.
// ----------------------------------------------------------------------------

#define T_STEPS  512
#define DIN      128
#define DST      128
#define DHID     512
#define NCL      32
#define CSZ      4
#define ROWS     8
#define NTHREADS 256

typedef unsigned long long u64;

#define FMA2(acc, s, w) asm("fma.rn.f32x2 %0, %1, %2, %0;" : "+l"(acc) : "l"(s), "l"(w))
#define PACK2(d, v)     asm("mov.b64 %0, {%1, %1};"        : "=l"(d)   : "r"(__float_as_uint(v)))

// precomputed x@W1x : [B*T][DHID] = 268 MB
__device__ float g_pre[(size_t)256 * T_STEPS * DHID];
// double-buffered per-rank partial states (1 MB)
__device__ float g_pstate[2][NCL][CSZ][ROWS][DST];

static __device__ __forceinline__ float4 f4add(float4 a, float4 b) {
    return make_float4(a.x + b.x, a.y + b.y, a.z + b.z, a.w + b.w);
}

// ============================================================================
// Prolog: pre = x @ W1x.  M=131072, K=128 (resident), N=512 (4 col tiles).
// CTA tile: 64 rows x 128 cols. block 256 = 16x16, thread = 4 rows x 8 cols.
// ============================================================================
#define PRE_SMEM_FLOATS (64 * 128 + 128 * 128)   // xs + ws = 98304 B

__global__ void __launch_bounds__(256, 2)
pre_kernel(const float* __restrict__ x, const float* __restrict__ W1)
{
    extern __shared__ float sm[];
    float* xs = sm;            // [64][128]   rows m, k contiguous
    float* ws = sm + 8192;     // [128][128]  k rows, cols contiguous

    const int tid = threadIdx.x;
    const size_t m0 = (size_t)blockIdx.x * 64;
    const int c0 = blockIdx.y * 128;

    const float4* xin = (const float4*)(x + m0 * DIN);
    for (int i = tid; i < 2048; i += 256) ((float4*)xs)[i] = xin[i];
    for (int i = tid; i < 128 * 32; i += 256) {
        int r = i >> 5, c4 = (i & 31) << 2;
        *(float4*)(ws + r * 128 + c4) = *(const float4*)(W1 + r * DHID + c0 + c4);
    }
    __syncthreads();

    const int tx = tid & 15, ty = tid >> 4;
    const float* xrow = xs + ty * 4 * 128;
    const float* wcol = ws + tx * 8;

    ulonglong2 acc[4][2];
    #pragma unroll
    for (int r = 0; r < 4; ++r) { acc[r][0].x = acc[r][0].y = 0ull;
                                  acc[r][1].x = acc[r][1].y = 0ull; }

    #pragma unroll 4
    for (int k = 0; k < 128; k += 4) {
        float4 av[4];
        #pragma unroll
        for (int r = 0; r < 4; ++r)
            av[r] = *(const float4*)(xrow + r * 128 + k);
        #pragma unroll
        for (int kk = 0; kk < 4; ++kk) {
            ulonglong2 wA = *(const ulonglong2*)(wcol + (k + kk) * 128);
            ulonglong2 wB = *(const ulonglong2*)(wcol + (k + kk) * 128 + 4);
            #pragma unroll
            for (int r = 0; r < 4; ++r) {
                float s = (kk == 0) ? av[r].x : (kk == 1) ? av[r].y
                        : (kk == 2) ? av[r].z : av[r].w;
                u64 sp; PACK2(sp, s);
                FMA2(acc[r][0].x, sp, wA.x);
                FMA2(acc[r][0].y, sp, wA.y);
                FMA2(acc[r][1].x, sp, wB.x);
                FMA2(acc[r][1].y, sp, wB.y);
            }
        }
    }

    float* outp = g_pre + (m0 + ty * 4) * DHID + c0 + tx * 8;
    #pragma unroll
    for (int r = 0; r < 4; ++r) {
        *(ulonglong2*)(outp + r * DHID)     = acc[r][0];
        *(ulonglong2*)(outp + r * DHID + 4) = acc[r][1];
    }
}

// ============================================================================
// Main sequential kernel.
// smem (floats):
//   W1a [128][128] @ 0      (64KB)  row = local a-k (global k = 128 + row)
//   W2s [128][128] @ 16384  (64KB)  row = local hidden j
//   hp  [8][8][128]@ 32768  (32KB)  8 K-chunk partial buffers
//   a_s [8][128]   @ 40960  ( 4KB)
//   h_s [8][128]   @ 41984  ( 4KB)
// ============================================================================
#define SMEM_FLOATS 43008    // 172032 B

__global__ void __cluster_dims__(CSZ, 1, 1) __launch_bounds__(NTHREADS, 1)
rnn_kernel(const float* __restrict__ a0,
           const float* __restrict__ W1, const float* __restrict__ b1,
           const float* __restrict__ W2, const float* __restrict__ b2,
           float* __restrict__ out)
{
    extern __shared__ float sm[];
    float* W1a = sm;
    float* W2s = sm + 16384;
    float* hp  = sm + 32768;
    float* a_s = sm + 40960;
    float* h_s = sm + 41984;

    const int tid   = threadIdx.x;
    const int lane  = tid & 31;
    const int wid   = tid >> 5;
    const int bx    = blockIdx.x;
    const int crank = bx & (CSZ - 1);
    const int gcl   = bx >> 2;
    const int rowbase = gcl * ROWS;
    const int jbase   = crank * 128;

    // ---- prologue: resident weights + initial state ----
    for (int i = tid; i < 128 * 32; i += NTHREADS) {       // W1a = W1 rows 128..255
        int row = i >> 5, c4 = (i & 31) << 2;
        *(float4*)(W1a + row * 128 + c4) =
            *(const float4*)(W1 + (size_t)(128 + row) * DHID + jbase + c4);
    }
    for (int i = tid; i < 4096; i += NTHREADS)
        ((float4*)W2s)[i] = ((const float4*)(W2 + (size_t)jbase * DST))[i];
    for (int i = tid; i < 256; i += NTHREADS)
        ((float4*)a_s)[i] = ((const float4*)(a0 + (size_t)rowbase * DST))[i];

    // combine mapping: warp = row, lane = 4 consecutive cols
    const int crow = wid;
    const int cj   = lane * 4;
    const float4 rb1 = *(const float4*)(b1 + jbase + cj);
    const float4 rb2 = *(const float4*)(b2 + cj);

    // GEMM mapping: warp = 16-wide K chunk, all 8 rows
    const int kbase = wid * 16;
    const float* g1_wr = W1a + kbase * 128 + cj;
    const float* g2_wr = W2s + kbase * 128 + cj;
    float* hpo = hp + wid * 1024 + cj;

    // pre stream for (row crow, cols jbase+cj), step stride DHID
    const float* prep = g_pre + ((size_t)(rowbase + crow) * T_STEPS) * DHID + jbase + cj;
    float4 prer = __ldcs((const float4*)prep);   // pre(0)

    float4 myp = make_float4(0.f, 0.f, 0.f, 0.f);

    __syncthreads();

    for (int t = 0; t < T_STEPS; ++t) {
        // ---- stage 1: fold step t-1 state into a ----
        if (t > 0) {
            const int pb = (t - 1) & 1;
            float4 acc = myp;
            #pragma unroll
            for (int r = 0; r < CSZ; ++r) {
                if (r == crank) continue;
                acc = f4add(acc, __ldcg((const float4*)&g_pstate[pb][gcl][r][crow][cj]));
            }
            float4 av = *(float4*)(a_s + crow * DST + cj);
            av.x += acc.x + rb2.x;  av.y += acc.y + rb2.y;
            av.z += acc.z + rb2.z;  av.w += acc.w + rb2.w;
            *(float4*)(a_s + crow * DST + cj) = av;
        }
        __syncthreads();

        // ---- G1a: a-part preact partials, warp = 16-k chunk x 8 rows ----
        {
            ulonglong2 acc[ROWS];
            #pragma unroll
            for (int r = 0; r < ROWS; ++r) { acc[r].x = 0ull; acc[r].y = 0ull; }
            #pragma unroll
            for (int kb = 0; kb < 4; ++kb) {
                float4 av[ROWS];
                #pragma unroll
                for (int r = 0; r < ROWS; ++r)
                    av[r] = *(const float4*)(a_s + r * 128 + kbase + kb * 4);
                const float* wk = g1_wr + kb * 4 * 128;
                #pragma unroll
                for (int kk = 0; kk < 4; ++kk) {
                    ulonglong2 w = *(const ulonglong2*)(wk + kk * 128);
                    #pragma unroll
                    for (int r = 0; r < ROWS; ++r) {
                        float s = (kk == 0) ? av[r].x : (kk == 1) ? av[r].y
                                : (kk == 2) ? av[r].z : av[r].w;
                        u64 sp; PACK2(sp, s);
                        FMA2(acc[r].x, sp, w.x);
                        FMA2(acc[r].y, sp, w.y);
                    }
                }
            }
            #pragma unroll
            for (int r = 0; r < ROWS; ++r)
                *(ulonglong2*)(hpo + r * 128) = acc[r];
        }
        __syncthreads();

        // ---- combine: preact = sum(8 partials) + pre + b1 -> tanh -> h ----
        {
            const float* hb = hp + crow * 128 + cj;
            float4 s = prer;
            #pragma unroll
            for (int q = 0; q < 8; ++q)
                s = f4add(s, *(const float4*)(hb + q * 1024));
            float4 hv;
            hv.x = tanhf(s.x + rb1.x);
            hv.y = tanhf(s.y + rb1.y);
            hv.z = tanhf(s.z + rb1.z);
            hv.w = tanhf(s.w + rb1.w);
            *(float4*)(h_s + crow * 128 + cj) = hv;
        }
        __syncthreads();

        // ---- G2: state partials, warp = 16-j chunk x 8 rows ----
        {
            ulonglong2 acc[ROWS];
            #pragma unroll
            for (int r = 0; r < ROWS; ++r) { acc[r].x = 0ull; acc[r].y = 0ull; }
            #pragma unroll
            for (int kb = 0; kb < 4; ++kb) {
                float4 av[ROWS];
                #pragma unroll
                for (int r = 0; r < ROWS; ++r)
                    av[r] = *(const float4*)(h_s + r * 128 + kbase + kb * 4);
                const float* wk = g2_wr + kb * 4 * 128;
                #pragma unroll
                for (int kk = 0; kk < 4; ++kk) {
                    ulonglong2 w = *(const ulonglong2*)(wk + kk * 128);
                    #pragma unroll
                    for (int r = 0; r < ROWS; ++r) {
                        float s = (kk == 0) ? av[r].x : (kk == 1) ? av[r].y
                                : (kk == 2) ? av[r].z : av[r].w;
                        u64 sp; PACK2(sp, s);
                        FMA2(acc[r].x, sp, w.x);
                        FMA2(acc[r].y, sp, w.y);
                    }
                }
            }
            #pragma unroll
            for (int r = 0; r < ROWS; ++r)
                *(ulonglong2*)(hpo + r * 128) = acc[r];
        }
        __syncthreads();

        // ---- combine G2 -> my partial state; publish; prefetch pre(t+1) ----
        {
            const float* hb = hp + crow * 128 + cj;
            float4 s = make_float4(0.f, 0.f, 0.f, 0.f);
            #pragma unroll
            for (int q = 0; q < 8; ++q)
                s = f4add(s, *(const float4*)(hb + q * 1024));
            myp = s;
            __stcg((float4*)&g_pstate[t & 1][gcl][crank][crow][cj], myp);
            if (t + 1 < T_STEPS)
                prer = __ldcs((const float4*)(prep + (size_t)(t + 1) * DHID));
        }
        // release/acquire cluster barrier orders the .cg exchange
        asm volatile("barrier.cluster.arrive.aligned;" ::: "memory");
        asm volatile("barrier.cluster.wait.aligned;"   ::: "memory");
    }

    // ---- epilogue ----
    {
        const int pb = (T_STEPS - 1) & 1;
        float4 acc = myp;
        #pragma unroll
        for (int r = 0; r < CSZ; ++r) {
            if (r == crank) continue;
            acc = f4add(acc, __ldcg((const float4*)&g_pstate[pb][gcl][r][crow][cj]));
        }
        float4 av = *(float4*)(a_s + crow * DST + cj);
        av.x += acc.x + rb2.x;  av.y += acc.y + rb2.y;
        av.z += acc.z + rb2.z;  av.w += acc.w + rb2.w;
        if (crank == 0)
            *(float4*)(out + (size_t)(rowbase + crow) * DST + cj) = av;
    }
}

extern "C" void kernel_launch(void* const* d_in, const int* in_sizes, int n_in,
                              void* d_out, int out_size) {
    const float* x  = (const float*)d_in[0];
    const float* a0 = (const float*)d_in[1];
    const float* W1 = (const float*)d_in[2];
    const float* b1 = (const float*)d_in[3];
    const float* W2 = (const float*)d_in[4];
    const float* b2 = (const float*)d_in[5];
    float* out = (float*)d_out;

    const size_t pre_smem = PRE_SMEM_FLOATS * sizeof(float);   // 98304 B
    cudaFuncSetAttribute(pre_kernel, cudaFuncAttributeMaxDynamicSharedMemorySize,
                         (int)pre_smem);
    dim3 pgrid(2048, 4);
    pre_kernel<<<pgrid, 256, pre_smem>>>(x, W1);

    const size_t smem = SMEM_FLOATS * sizeof(float);           // 172032 B
    cudaFuncSetAttribute(rnn_kernel, cudaFuncAttributeMaxDynamicSharedMemorySize,
                         (int)smem);
    rnn_kernel<<<NCL * CSZ, NTHREADS, smem>>>(a0, W1, b1, W2, b2, out);
}

// round 9
// speedup vs baseline: 1.1742x; 1.1742x over previous
#include <cuda_runtime.h>
#include <cstdint>
#include <cstddef>

// ----------------------------------------------------------------------------
// Round 9 = Round 7 design + x-prefetch off-by-one fix.
//   a <- a + W2^T tanh([x_t; a] @ W1 + b1) + b2,  512 steps.
// 32 clusters x 4 CTAs; cluster owns 8 batch rows; CTA rank owns hidden slice
// [128r, 128r+128).
//   G1 (K=256): warp w owns k-chunk [32w,32w+32); weight slice in REGISTERS
//     (32 k x 4 j per thread = 128 regs) -> zero G1 weight LDS traffic.
//   G2 (K=128): warp w owns j-chunk [16w,16w+16); weights from smem (64KB).
// Partials: 8 per-warp buffers, single round; 4 syncthreads + 1 cluster
// barrier per step. Cross-CTA state reduction through L2 (.cg), double-buffered.
// ----------------------------------------------------------------------------

#define T_STEPS  512
#define DIN      128
#define DST      128
#define DHID     512
#define NCL      32
#define CSZ      4
#define ROWS     8
#define NTHREADS 256

typedef unsigned long long u64;

#define FMA2(acc, s, w) asm("fma.rn.f32x2 %0, %1, %2, %0;" : "+l"(acc) : "l"(s), "l"(w))
#define PACK2(d, v)     asm("mov.b64 %0, {%1, %1};"        : "=l"(d)   : "r"(__float_as_uint(v)))

// double-buffered per-rank partial states (1 MB static scratch)
__device__ float g_pstate[2][NCL][CSZ][ROWS][DST];

// smem layout (floats):
//   W2s [128][128] @ 0      (64KB)  row = local hidden j
//   hp  [8][8][128]@ 16384  (32KB)  8 per-warp partial buffers
//   a_s [8][128]   @ 24576  ( 4KB)
//   x_s [8][128]   @ 25600  ( 4KB)
//   h_s [8][128]   @ 26624  ( 4KB)
#define SMEM_FLOATS 27648    // 110592 B

static __device__ __forceinline__ float4 f4add(float4 a, float4 b) {
    return make_float4(a.x + b.x, a.y + b.y, a.z + b.z, a.w + b.w);
}

__global__ void __cluster_dims__(CSZ, 1, 1) __launch_bounds__(NTHREADS, 1)
rnn_kernel(const float* __restrict__ x,  const float* __restrict__ a0,
           const float* __restrict__ W1, const float* __restrict__ b1,
           const float* __restrict__ W2, const float* __restrict__ b2,
           float* __restrict__ out)
{
    extern __shared__ float sm[];
    float* W2s = sm;
    float* hp  = sm + 16384;
    float* a_s = sm + 24576;
    float* x_s = sm + 25600;
    float* h_s = sm + 26624;

    const int tid   = threadIdx.x;
    const int lane  = tid & 31;
    const int wid   = tid >> 5;
    const int bx    = blockIdx.x;
    const int crank = bx & (CSZ - 1);
    const int gcl   = bx >> 2;
    const int rowbase = gcl * ROWS;
    const int jbase   = crank * 128;
    const int cj      = lane * 4;

    // ---- G1 weights into registers: 32 k-rows x 4 j-cols per thread ----
    // warp w owns global k in [32w, 32w+32); W1 row = global k (x:0..127, a:128..255)
    ulonglong2 w1r[32];
    {
        const float* wsrc = W1 + (size_t)(32 * wid) * DHID + jbase + cj;
        #pragma unroll
        for (int r = 0; r < 32; ++r)
            w1r[r] = *(const ulonglong2*)(wsrc + (size_t)r * DHID);
    }

    // ---- prologue: smem-resident W2 slice, initial state, x(0) ----
    for (int i = tid; i < 4096; i += NTHREADS)
        ((float4*)W2s)[i] = ((const float4*)(W2 + (size_t)jbase * DST))[i];
    for (int i = tid; i < 256; i += NTHREADS)
        ((float4*)a_s)[i] = ((const float4*)(a0 + (size_t)rowbase * DST))[i];
    for (int i = tid; i < 256; i += NTHREADS) {
        int r = i >> 5, c4 = (i & 31) << 2;
        *(float4*)(x_s + r * 128 + c4) =
            *(const float4*)(x + (size_t)(rowbase + r) * (size_t)(T_STEPS * DIN) + c4);
    }

    // combine/publish mapping: warp = row, lane = 4 consecutive cols
    const int crow = wid;
    const float4 rb1 = *(const float4*)(b1 + jbase + cj);
    const float4 rb2 = *(const float4*)(b2 + cj);

    // G1 activation source for this warp's k-chunk
    const float* g1_act = (wid < 4) ? (x_s + wid * 32) : (a_s + (wid - 4) * 32);
    // G2 smem weights: warp owns j-chunk [16w, 16w+16)
    const float* g2_wr = W2s + (wid * 16) * 128 + cj;
    float* hpo = hp + wid * 1024 + cj;

    const float* xrow = x + (size_t)(rowbase + crow) * (size_t)(T_STEPS * DIN) + cj;
    float4 xr  = (T_STEPS > 1) ? *(const float4*)(xrow + DIN)
                               : make_float4(0.f, 0.f, 0.f, 0.f);   // x(1)
    float4 myp = make_float4(0.f, 0.f, 0.f, 0.f);

    __syncthreads();

    for (int t = 0; t < T_STEPS; ++t) {
        // ---- stage 1: fold step t-1 state into a; stage x(t) ----
        if (t > 0) {
            const int pb = (t - 1) & 1;
            float4 acc = myp;
            #pragma unroll
            for (int r = 0; r < CSZ; ++r) {
                if (r == crank) continue;
                acc = f4add(acc, __ldcg((const float4*)&g_pstate[pb][gcl][r][crow][cj]));
            }
            float4 av = *(float4*)(a_s + crow * DST + cj);
            av.x += acc.x + rb2.x;  av.y += acc.y + rb2.y;
            av.z += acc.z + rb2.z;  av.w += acc.w + rb2.w;
            *(float4*)(a_s + crow * DST + cj) = av;
            *(float4*)(x_s + crow * DIN + cj) = xr;   // xr == x(t) here
        }
        __syncthreads();

        // ---- G1: preact partials, warp = 32-k chunk x 8 rows, REG weights ----
        {
            ulonglong2 acc[ROWS];
            #pragma unroll
            for (int r = 0; r < ROWS; ++r) { acc[r].x = 0ull; acc[r].y = 0ull; }
            #pragma unroll
            for (int kb = 0; kb < 8; ++kb) {
                #pragma unroll
                for (int half = 0; half < 2; ++half) {
                    float4 av[4];
                    #pragma unroll
                    for (int r = 0; r < 4; ++r)
                        av[r] = *(const float4*)(g1_act + (half * 4 + r) * 128 + kb * 4);
                    #pragma unroll
                    for (int kk = 0; kk < 4; ++kk) {
                        const ulonglong2 w = w1r[kb * 4 + kk];
                        #pragma unroll
                        for (int r = 0; r < 4; ++r) {
                            float s = (kk == 0) ? av[r].x : (kk == 1) ? av[r].y
                                    : (kk == 2) ? av[r].z : av[r].w;
                            u64 sp; PACK2(sp, s);
                            FMA2(acc[half * 4 + r].x, sp, w.x);
                            FMA2(acc[half * 4 + r].y, sp, w.y);
                        }
                    }
                }
            }
            #pragma unroll
            for (int r = 0; r < ROWS; ++r)
                *(ulonglong2*)(hpo + r * 128) = acc[r];
        }
        __syncthreads();

        // ---- combine: preact = sum(8 partials) + b1 -> tanh -> h_s ----
        {
            const float* hb = hp + crow * 128 + cj;
            float4 s = *(const float4*)(hb);
            #pragma unroll
            for (int q = 1; q < 8; ++q)
                s = f4add(s, *(const float4*)(hb + q * 1024));
            float4 hv;
            hv.x = tanhf(s.x + rb1.x);
            hv.y = tanhf(s.y + rb1.y);
            hv.z = tanhf(s.z + rb1.z);
            hv.w = tanhf(s.w + rb1.w);
            *(float4*)(h_s + crow * 128 + cj) = hv;
        }
        __syncthreads();

        // ---- G2: state partials, warp = 16-j chunk x 8 rows, smem weights ----
        {
            ulonglong2 acc[ROWS];
            #pragma unroll
            for (int r = 0; r < ROWS; ++r) { acc[r].x = 0ull; acc[r].y = 0ull; }
            const float* act2 = h_s + wid * 16;
            #pragma unroll
            for (int kb = 0; kb < 4; ++kb) {
                #pragma unroll
                for (int half = 0; half < 2; ++half) {
                    float4 av[4];
                    #pragma unroll
                    for (int r = 0; r < 4; ++r)
                        av[r] = *(const float4*)(act2 + (half * 4 + r) * 128 + kb * 4);
                    const float* wk = g2_wr + kb * 4 * 128;
                    #pragma unroll
                    for (int kk = 0; kk < 4; ++kk) {
                        const ulonglong2 w = *(const ulonglong2*)(wk + kk * 128);
                        #pragma unroll
                        for (int r = 0; r < 4; ++r) {
                            float s = (kk == 0) ? av[r].x : (kk == 1) ? av[r].y
                                    : (kk == 2) ? av[r].z : av[r].w;
                            u64 sp; PACK2(sp, s);
                            FMA2(acc[half * 4 + r].x, sp, w.x);
                            FMA2(acc[half * 4 + r].y, sp, w.y);
                        }
                    }
                }
            }
            #pragma unroll
            for (int r = 0; r < ROWS; ++r)
                *(ulonglong2*)(hpo + r * 128) = acc[r];
        }
        __syncthreads();

        // ---- combine G2 -> my partial state; publish via L2; prefetch x ----
        {
            const float* hb = hp + crow * 128 + cj;
            float4 s = *(const float4*)(hb);
            #pragma unroll
            for (int q = 1; q < 8; ++q)
                s = f4add(s, *(const float4*)(hb + q * 1024));
            myp = s;
            __stcg((float4*)&g_pstate[t & 1][gcl][crank][crow][cj], myp);
            // xr was consumed (as x(t)) at stage 1 of THIS iteration;
            // next consumption is stage 1 of t+1, which needs x(t+1).
            if (t + 1 < T_STEPS)
                xr = *(const float4*)(xrow + (size_t)(t + 1) * DIN);
        }
        // release/acquire cluster barrier orders the .cg exchange
        asm volatile("barrier.cluster.arrive.aligned;" ::: "memory");
        asm volatile("barrier.cluster.wait.aligned;"   ::: "memory");
    }

    // ---- epilogue: fold final state; rank 0 writes out ----
    {
        const int pb = (T_STEPS - 1) & 1;
        float4 acc = myp;
        #pragma unroll
        for (int r = 0; r < CSZ; ++r) {
            if (r == crank) continue;
            acc = f4add(acc, __ldcg((const float4*)&g_pstate[pb][gcl][r][crow][cj]));
        }
        float4 av = *(float4*)(a_s + crow * DST + cj);
        av.x += acc.x + rb2.x;  av.y += acc.y + rb2.y;
        av.z += acc.z + rb2.z;  av.w += acc.w + rb2.w;
        if (crank == 0)
            *(float4*)(out + (size_t)(rowbase + crow) * DST + cj) = av;
    }
}

extern "C" void kernel_launch(void* const* d_in, const int* in_sizes, int n_in,
                              void* d_out, int out_size) {
    const float* x  = (const float*)d_in[0];
    const float* a0 = (const float*)d_in[1];
    const float* W1 = (const float*)d_in[2];
    const float* b1 = (const float*)d_in[3];
    const float* W2 = (const float*)d_in[4];
    const float* b2 = (const float*)d_in[5];
    float* out = (float*)d_out;

    const size_t smem = SMEM_FLOATS * sizeof(float);   // 110592 B
    cudaFuncSetAttribute(rnn_kernel, cudaFuncAttributeMaxDynamicSharedMemorySize,
                         (int)smem);
    rnn_kernel<<<NCL * CSZ, NTHREADS, smem>>>(x, a0, W1, b1, W2, b2, out);
}

// round 10
// speedup vs baseline: 1.2316x; 1.0489x over previous
#include <cuda_runtime.h>
#include <cstdint>
#include <cstddef>

// ----------------------------------------------------------------------------
// Round 10: warp-specialized overlap of the cluster barrier.
//   a <- a + W2^T tanh([x_t; a] @ W1 + b1) + b2,  512 steps.
// 32 clusters x 4 CTAs; cluster owns 8 batch rows; CTA rank owns hidden slice
// [128r, 128r+128). G1 weights in registers (32k x 4j per thread).
//
// Warp roles per step:
//   x-warps (0-3): G1x for step t+1 runs AFTER cluster.arrive, overlapping the
//                  barrier settle + other ranks' publish + the state fold.
//   a-warps (4-7): state fold (2 rows each, 4-rank L2 ldcg) + x staging, G1a.
//   all 8:         C1 (tanh), G2, C2 (combine + publish).
// x double-buffered in smem; G1x partials in dedicated hp_x buffer.
// ----------------------------------------------------------------------------

#define T_STEPS  512
#define DIN      128
#define DST      128
#define DHID     512
#define NCL      32
#define CSZ      4
#define ROWS     8
#define NTHREADS 256

typedef unsigned long long u64;

#define FMA2(acc, s, w) asm("fma.rn.f32x2 %0, %1, %2, %0;" : "+l"(acc) : "l"(s), "l"(w))
#define PACK2(d, v)     asm("mov.b64 %0, {%1, %1};"        : "=l"(d)   : "r"(__float_as_uint(v)))

// double-buffered per-rank partial states (1 MB static scratch)
__device__ float g_pstate[2][NCL][CSZ][ROWS][DST];

// smem layout (floats):
//   W2s  [128][128] @ 0      (64KB)
//   hp   [8][8][128]@ 16384  (32KB)  G1a (bufs 4-7) + G2 (bufs 0-7) partials
//   hp_x [4][8][128]@ 24576  (16KB)  G1x partials (written a step ahead)
//   a_s  [8][128]   @ 28672  ( 4KB)
//   x2   [2][8][128]@ 29696  ( 8KB)  double-buffered x
//   h_s  [8][128]   @ 31744  ( 4KB)
#define SMEM_FLOATS 32768    // 131072 B

static __device__ __forceinline__ float4 f4add(float4 a, float4 b) {
    return make_float4(a.x + b.x, a.y + b.y, a.z + b.z, a.w + b.w);
}

// 32-k x 8-row x 4-col GEMM partial with register weights
static __device__ __forceinline__ void gemm_g1(
    const float* __restrict__ act, const ulonglong2* __restrict__ w,
    float* __restrict__ hpo)
{
    ulonglong2 acc[ROWS];
    #pragma unroll
    for (int r = 0; r < ROWS; ++r) { acc[r].x = 0ull; acc[r].y = 0ull; }
    #pragma unroll
    for (int kb = 0; kb < 8; ++kb) {
        #pragma unroll
        for (int half = 0; half < 2; ++half) {
            float4 av[4];
            #pragma unroll
            for (int r = 0; r < 4; ++r)
                av[r] = *(const float4*)(act + (half * 4 + r) * 128 + kb * 4);
            #pragma unroll
            for (int kk = 0; kk < 4; ++kk) {
                const ulonglong2 ww = w[kb * 4 + kk];
                #pragma unroll
                for (int r = 0; r < 4; ++r) {
                    float s = (kk == 0) ? av[r].x : (kk == 1) ? av[r].y
                            : (kk == 2) ? av[r].z : av[r].w;
                    u64 sp; PACK2(sp, s);
                    FMA2(acc[half * 4 + r].x, sp, ww.x);
                    FMA2(acc[half * 4 + r].y, sp, ww.y);
                }
            }
        }
    }
    #pragma unroll
    for (int r = 0; r < ROWS; ++r)
        *(ulonglong2*)(hpo + r * 128) = acc[r];
}

__global__ void __cluster_dims__(CSZ, 1, 1) __launch_bounds__(NTHREADS, 1)
rnn_kernel(const float* __restrict__ x,  const float* __restrict__ a0,
           const float* __restrict__ W1, const float* __restrict__ b1,
           const float* __restrict__ W2, const float* __restrict__ b2,
           float* __restrict__ out)
{
    extern __shared__ float sm[];
    float* W2s  = sm;
    float* hp   = sm + 16384;
    float* hp_x = sm + 24576;
    float* a_s  = sm + 28672;
    float* x2   = sm + 29696;   // [2][8][128]
    float* h_s  = sm + 31744;

    const int tid   = threadIdx.x;
    const int lane  = tid & 31;
    const int wid   = tid >> 5;
    const int bx    = blockIdx.x;
    const int crank = bx & (CSZ - 1);
    const int gcl   = bx >> 2;
    const int rowbase = gcl * ROWS;
    const int jbase   = crank * 128;
    const int cj      = lane * 4;

    // ---- G1 weights into registers: warp w owns global k in [32w, 32w+32) ----
    // warps 0-3: x rows (k 0..127); warps 4-7: a rows (k 128..255)
    ulonglong2 w1r[32];
    {
        const float* wsrc = W1 + (size_t)(32 * wid) * DHID + jbase + cj;
        #pragma unroll
        for (int r = 0; r < 32; ++r)
            w1r[r] = *(const ulonglong2*)(wsrc + (size_t)r * DHID);
    }

    // ---- prologue: W2 slice, a0, x(0) into x2[0] ----
    for (int i = tid; i < 4096; i += NTHREADS)
        ((float4*)W2s)[i] = ((const float4*)(W2 + (size_t)jbase * DST))[i];
    for (int i = tid; i < 256; i += NTHREADS)
        ((float4*)a_s)[i] = ((const float4*)(a0 + (size_t)rowbase * DST))[i];
    for (int i = tid; i < 256; i += NTHREADS) {
        int r = i >> 5, c4 = (i & 31) << 2;
        *(float4*)(x2 + r * 128 + c4) =
            *(const float4*)(x + (size_t)(rowbase + r) * (size_t)(T_STEPS * DIN) + c4);
    }

    const int crow = wid;
    const float4 rb1 = *(const float4*)(b1 + jbase + cj);
    const float4 rb2 = *(const float4*)(b2 + cj);

    // a-warp fold/staging rows
    const int r0 = (wid - 4) * 2;           // valid for wid>=4
    const float* xrow0 = x + (size_t)(rowbase + r0)     * (size_t)(T_STEPS * DIN) + cj;
    const float* xrow1 = x + (size_t)(rowbase + r0 + 1) * (size_t)(T_STEPS * DIN) + cj;
    float4 xr0 = make_float4(0.f,0.f,0.f,0.f), xr1 = xr0;
    if (wid >= 4) {                          // x(1) for S1(0) staging
        xr0 = *(const float4*)(xrow0 + DIN);
        xr1 = *(const float4*)(xrow1 + DIN);
    }

    const float* g2_wr = W2s + (wid * 16) * 128 + cj;
    float* hpo = hp + wid * 1024 + cj;

    __syncthreads();

    // ---- G1x for step 0 (x-warps), using x2[0] ----
    if (wid < 4)
        gemm_g1(x2 + wid * 32, w1r, hp_x + wid * 1024 + cj);

    for (int t = 0; t < T_STEPS; ++t) {
        if (t > 0) {
            asm volatile("barrier.cluster.wait.aligned;" ::: "memory");
        }

        // ---- S1 (a-warps): fold state t-1 into a (2 rows), stage x(t+1) ----
        if (wid >= 4) {
            if (t > 0) {
                const int pb = (t - 1) & 1;
                #pragma unroll
                for (int rr = 0; rr < 2; ++rr) {
                    const int row = r0 + rr;
                    float4 acc = __ldcg((const float4*)&g_pstate[pb][gcl][0][row][cj]);
                    #pragma unroll
                    for (int r = 1; r < CSZ; ++r)
                        acc = f4add(acc, __ldcg((const float4*)&g_pstate[pb][gcl][r][row][cj]));
                    float4 av = *(float4*)(a_s + row * DST + cj);
                    av.x += acc.x + rb2.x;  av.y += acc.y + rb2.y;
                    av.z += acc.z + rb2.z;  av.w += acc.w + rb2.w;
                    *(float4*)(a_s + row * DST + cj) = av;
                }
            }
            if (t + 1 < T_STEPS) {
                float* xb = x2 + ((t + 1) & 1) * 1024;
                *(float4*)(xb + r0 * 128 + cj)       = xr0;   // x(t+1)
                *(float4*)(xb + (r0 + 1) * 128 + cj) = xr1;
                if (t + 2 < T_STEPS) {
                    xr0 = *(const float4*)(xrow0 + (size_t)(t + 2) * DIN);
                    xr1 = *(const float4*)(xrow1 + (size_t)(t + 2) * DIN);
                }
            }
        }
        __syncthreads();   // B1

        // ---- G1a (a-warps): a-part partials -> hp bufs 4..7 ----
        if (wid >= 4)
            gemm_g1(a_s + (wid - 4) * 32, w1r, hpo);
        __syncthreads();   // B2

        // ---- C1 (all): preact = hp_x[0..3] + hp[4..7] + b1 -> tanh -> h_s ----
        {
            const float* hbx = hp_x + crow * 128 + cj;
            const float* hba = hp   + crow * 128 + cj;
            float4 s = *(const float4*)(hbx);
            s = f4add(s, *(const float4*)(hbx + 1024));
            s = f4add(s, *(const float4*)(hbx + 2048));
            s = f4add(s, *(const float4*)(hbx + 3072));
            s = f4add(s, *(const float4*)(hba + 4096));
            s = f4add(s, *(const float4*)(hba + 5120));
            s = f4add(s, *(const float4*)(hba + 6144));
            s = f4add(s, *(const float4*)(hba + 7168));
            float4 hv;
            hv.x = tanhf(s.x + rb1.x);
            hv.y = tanhf(s.y + rb1.y);
            hv.z = tanhf(s.z + rb1.z);
            hv.w = tanhf(s.w + rb1.w);
            *(float4*)(h_s + crow * 128 + cj) = hv;
        }
        __syncthreads();   // B3

        // ---- G2 (all): warp = 16-j chunk x 8 rows, smem weights ----
        {
            ulonglong2 acc[ROWS];
            #pragma unroll
            for (int r = 0; r < ROWS; ++r) { acc[r].x = 0ull; acc[r].y = 0ull; }
            const float* act2 = h_s + wid * 16;
            #pragma unroll
            for (int kb = 0; kb < 4; ++kb) {
                #pragma unroll
                for (int half = 0; half < 2; ++half) {
                    float4 av[4];
                    #pragma unroll
                    for (int r = 0; r < 4; ++r)
                        av[r] = *(const float4*)(act2 + (half * 4 + r) * 128 + kb * 4);
                    const float* wk = g2_wr + kb * 4 * 128;
                    #pragma unroll
                    for (int kk = 0; kk < 4; ++kk) {
                        const ulonglong2 ww = *(const ulonglong2*)(wk + kk * 128);
                        #pragma unroll
                        for (int r = 0; r < 4; ++r) {
                            float s = (kk == 0) ? av[r].x : (kk == 1) ? av[r].y
                                    : (kk == 2) ? av[r].z : av[r].w;
                            u64 sp; PACK2(sp, s);
                            FMA2(acc[half * 4 + r].x, sp, ww.x);
                            FMA2(acc[half * 4 + r].y, sp, ww.y);
                        }
                    }
                }
            }
            #pragma unroll
            for (int r = 0; r < ROWS; ++r)
                *(ulonglong2*)(hpo + r * 128) = acc[r];
        }
        __syncthreads();   // B4

        // ---- C2 (all): combine -> publish my state partial for row crow ----
        {
            const float* hb = hp + crow * 128 + cj;
            float4 s = *(const float4*)(hb);
            #pragma unroll
            for (int q = 1; q < 8; ++q)
                s = f4add(s, *(const float4*)(hb + q * 1024));
            __stcg((float4*)&g_pstate[t & 1][gcl][crank][crow][cj], s);
        }
        asm volatile("barrier.cluster.arrive.aligned;" ::: "memory");

        // ---- G1x for step t+1 (x-warps) under the barrier shadow ----
        if (t + 1 < T_STEPS && wid < 4)
            gemm_g1(x2 + ((t + 1) & 1) * 1024 + wid * 32, w1r,
                    hp_x + wid * 1024 + cj);
    }

    // ---- epilogue: final wait, fold last state, rank 0 writes out ----
    asm volatile("barrier.cluster.wait.aligned;" ::: "memory");
    {
        const int pb = (T_STEPS - 1) & 1;
        float4 acc = __ldcg((const float4*)&g_pstate[pb][gcl][0][crow][cj]);
        #pragma unroll
        for (int r = 1; r < CSZ; ++r)
            acc = f4add(acc, __ldcg((const float4*)&g_pstate[pb][gcl][r][crow][cj]));
        float4 av = *(float4*)(a_s + crow * DST + cj);
        av.x += acc.x + rb2.x;  av.y += acc.y + rb2.y;
        av.z += acc.z + rb2.z;  av.w += acc.w + rb2.w;
        if (crank == 0)
            *(float4*)(out + (size_t)(rowbase + crow) * DST + cj) = av;
    }
}

extern "C" void kernel_launch(void* const* d_in, const int* in_sizes, int n_in,
                              void* d_out, int out_size) {
    const float* x  = (const float*)d_in[0];
    const float* a0 = (const float*)d_in[1];
    const float* W1 = (const float*)d_in[2];
    const float* b1 = (const float*)d_in[3];
    const float* W2 = (const float*)d_in[4];
    const float* b2 = (const float*)d_in[5];
    float* out = (float*)d_out;

    const size_t smem = SMEM_FLOATS * sizeof(float);   // 131072 B
    cudaFuncSetAttribute(rnn_kernel, cudaFuncAttributeMaxDynamicSharedMemorySize,
                         (int)smem);
    rnn_kernel<<<NCL * CSZ, NTHREADS, smem>>>(x, a0, W1, b1, W2, b2, out);
}

// round 11
// speedup vs baseline: 1.2516x; 1.0162x over previous
#include <cuda_runtime.h>
#include <cstdint>
#include <cstddef>

// ----------------------------------------------------------------------------
// Round 11: full shadow of barrier + fold latency; 2 warps/SMSP in all GEMMs.
//   a <- a + W2^T tanh([x_t; a] @ W1 + b1) + b2,  512 steps.
// 32 clusters x 4 CTAs; cluster owns 8 batch rows; CTA rank owns hidden slice
// [128r, 128r+128). All G1 weights in registers: per thread 16k x 4j for the
// x-part (w1x) + 16k x 4j for the a-part (w1a).
//
// Per-step schedule (all warps everywhere):
//   G1a -> B2 -> C1(16-buf combine,tanh) -> B3 -> G2 -> B4 ->
//   C2(publish .cg) -> cluster.arrive -> G1x(t+1) rows 0-3 -> cluster.wait ->
//   fold ldcg x4 -> G1x(t+1) rows 4-7 -> fold combine + x stage -> B1
// The barrier settle hides under G1x-A; the L2 fold latency under G1x-B.
// ----------------------------------------------------------------------------

#define T_STEPS  512
#define DIN      128
#define DST      128
#define DHID     512
#define NCL      32
#define CSZ      4
#define ROWS     8
#define NTHREADS 256

typedef unsigned long long u64;

#define FMA2(acc, s, w) asm("fma.rn.f32x2 %0, %1, %2, %0;" : "+l"(acc) : "l"(s), "l"(w))
#define PACK2(d, v)     asm("mov.b64 %0, {%1, %1};"        : "=l"(d)   : "r"(__float_as_uint(v)))

// double-buffered per-rank partial states (1 MB static scratch)
__device__ float g_pstate[2][NCL][CSZ][ROWS][DST];

// smem layout (floats):
//   W2s  [128][128] @ 0      (64KB)
//   hp   [8][8][128]@ 16384  (32KB)  G1a partials, then G2 partials
//   hp_x [8][8][128]@ 24576  (32KB)  G1x partials (written one step ahead)
//   a_s  [8][128]   @ 32768  ( 4KB)
//   x2   [2][8][128]@ 33792  ( 8KB)  double-buffered x
//   h_s  [8][128]   @ 35840  ( 4KB)
#define SMEM_FLOATS 36864    // 147456 B

static __device__ __forceinline__ float4 f4add(float4 a, float4 b) {
    return make_float4(a.x + b.x, a.y + b.y, a.z + b.z, a.w + b.w);
}

// 16-k x 4-row x 4-col GEMM partial with register weights.
// act: base of this warp's k-chunk (row stride 128). outp: partial buf + cj.
static __device__ __forceinline__ void gemm16_rows(
    const float* __restrict__ act, const ulonglong2* __restrict__ w,
    float* __restrict__ outp, int rlo)
{
    ulonglong2 acc[4];
    #pragma unroll
    for (int r = 0; r < 4; ++r) { acc[r].x = 0ull; acc[r].y = 0ull; }
    #pragma unroll
    for (int kb = 0; kb < 4; ++kb) {
        float4 av[4];
        #pragma unroll
        for (int r = 0; r < 4; ++r)
            av[r] = *(const float4*)(act + (rlo + r) * 128 + kb * 4);
        #pragma unroll
        for (int kk = 0; kk < 4; ++kk) {
            const ulonglong2 ww = w[kb * 4 + kk];
            #pragma unroll
            for (int r = 0; r < 4; ++r) {
                float s = (kk == 0) ? av[r].x : (kk == 1) ? av[r].y
                        : (kk == 2) ? av[r].z : av[r].w;
                u64 sp; PACK2(sp, s);
                FMA2(acc[r].x, sp, ww.x);
                FMA2(acc[r].y, sp, ww.y);
            }
        }
    }
    #pragma unroll
    for (int r = 0; r < 4; ++r)
        *(ulonglong2*)(outp + (rlo + r) * 128) = acc[r];
}

__global__ void __cluster_dims__(CSZ, 1, 1) __launch_bounds__(NTHREADS, 1)
rnn_kernel(const float* __restrict__ x,  const float* __restrict__ a0,
           const float* __restrict__ W1, const float* __restrict__ b1,
           const float* __restrict__ W2, const float* __restrict__ b2,
           float* __restrict__ out)
{
    extern __shared__ float sm[];
    float* W2s  = sm;
    float* hp   = sm + 16384;
    float* hp_x = sm + 24576;
    float* a_s  = sm + 32768;
    float* x2   = sm + 33792;   // [2][8][128]
    float* h_s  = sm + 35840;

    const int tid   = threadIdx.x;
    const int lane  = tid & 31;
    const int wid   = tid >> 5;
    const int bx    = blockIdx.x;
    const int crank = bx & (CSZ - 1);
    const int gcl   = bx >> 2;
    const int rowbase = gcl * ROWS;
    const int jbase   = crank * 128;
    const int cj      = lane * 4;

    // ---- G1 weights into registers ----
    // w1x: W1 rows [16*wid, 16*wid+16)          (x part, k = 0..127)
    // w1a: W1 rows [128 + 16*wid, 128+16*wid+16) (a part, k = 128..255)
    ulonglong2 w1x[16], w1a[16];
    {
        const float* ws = W1 + (size_t)(16 * wid) * DHID + jbase + cj;
        #pragma unroll
        for (int r = 0; r < 16; ++r)
            w1x[r] = *(const ulonglong2*)(ws + (size_t)r * DHID);
        const float* wa = W1 + (size_t)(128 + 16 * wid) * DHID + jbase + cj;
        #pragma unroll
        for (int r = 0; r < 16; ++r)
            w1a[r] = *(const ulonglong2*)(wa + (size_t)r * DHID);
    }

    // ---- prologue: W2 slice, a0, x(0) -> x2[0], x(1) -> x2[1], xr = x(2) ----
    for (int i = tid; i < 4096; i += NTHREADS)
        ((float4*)W2s)[i] = ((const float4*)(W2 + (size_t)jbase * DST))[i];
    for (int i = tid; i < 256; i += NTHREADS)
        ((float4*)a_s)[i] = ((const float4*)(a0 + (size_t)rowbase * DST))[i];
    for (int i = tid; i < 256; i += NTHREADS) {
        int r = i >> 5, c4 = (i & 31) << 2;
        *(float4*)(x2 + r * 128 + c4) =
            *(const float4*)(x + (size_t)(rowbase + r) * (size_t)(T_STEPS * DIN) + c4);
    }

    const int crow = wid;                 // this warp's batch row
    const float4 rb1 = *(const float4*)(b1 + jbase + cj);
    const float4 rb2 = *(const float4*)(b2 + cj);

    const float* xrow = x + (size_t)(rowbase + crow) * (size_t)(T_STEPS * DIN) + cj;
    // stage x(1) into x2[1]
    *(float4*)(x2 + 1024 + crow * 128 + cj) = *(const float4*)(xrow + DIN);
    float4 xr = *(const float4*)(xrow + 2 * DIN);   // x(2)

    const float* g2_wr = W2s + (wid * 16) * 128 + cj;
    float* hpo  = hp   + wid * 1024 + cj;
    float* hpxo = hp_x + wid * 1024 + cj;

    __syncthreads();

    // ---- G1x for step 0 (all warps, both halves) ----
    gemm16_rows(x2 + wid * 16, w1x, hpxo, 0);
    gemm16_rows(x2 + wid * 16, w1x, hpxo, 4);
    __syncthreads();   // B1 (step 0 entry)

    for (int t = 0; t < T_STEPS; ++t) {
        // ---- G1a: a-part preact partials, warp = 16-k chunk x 8 rows ----
        gemm16_rows(a_s + wid * 16, w1a, hpo, 0);
        gemm16_rows(a_s + wid * 16, w1a, hpo, 4);
        __syncthreads();   // B2

        // ---- C1: preact = sum(8 hp_x + 8 hp) + b1 -> tanh -> h_s ----
        {
            const float* hbx = hp_x + crow * 128 + cj;
            const float* hba = hp   + crow * 128 + cj;
            float4 s = *(const float4*)(hbx);
            #pragma unroll
            for (int q = 1; q < 8; ++q)
                s = f4add(s, *(const float4*)(hbx + q * 1024));
            #pragma unroll
            for (int q = 0; q < 8; ++q)
                s = f4add(s, *(const float4*)(hba + q * 1024));
            float4 hv;
            hv.x = tanhf(s.x + rb1.x);
            hv.y = tanhf(s.y + rb1.y);
            hv.z = tanhf(s.z + rb1.z);
            hv.w = tanhf(s.w + rb1.w);
            *(float4*)(h_s + crow * 128 + cj) = hv;
        }
        __syncthreads();   // B3

        // ---- G2: warp = 16-j chunk x 8 rows, smem weights ----
        {
            ulonglong2 acc[ROWS];
            #pragma unroll
            for (int r = 0; r < ROWS; ++r) { acc[r].x = 0ull; acc[r].y = 0ull; }
            const float* act2 = h_s + wid * 16;
            #pragma unroll
            for (int kb = 0; kb < 4; ++kb) {
                #pragma unroll
                for (int half = 0; half < 2; ++half) {
                    float4 av[4];
                    #pragma unroll
                    for (int r = 0; r < 4; ++r)
                        av[r] = *(const float4*)(act2 + (half * 4 + r) * 128 + kb * 4);
                    const float* wk = g2_wr + kb * 4 * 128;
                    #pragma unroll
                    for (int kk = 0; kk < 4; ++kk) {
                        const ulonglong2 ww = *(const ulonglong2*)(wk + kk * 128);
                        #pragma unroll
                        for (int r = 0; r < 4; ++r) {
                            float s = (kk == 0) ? av[r].x : (kk == 1) ? av[r].y
                                    : (kk == 2) ? av[r].z : av[r].w;
                            u64 sp; PACK2(sp, s);
                            FMA2(acc[half * 4 + r].x, sp, ww.x);
                            FMA2(acc[half * 4 + r].y, sp, ww.y);
                        }
                    }
                }
            }
            #pragma unroll
            for (int r = 0; r < ROWS; ++r)
                *(ulonglong2*)(hpo + r * 128) = acc[r];
        }
        __syncthreads();   // B4

        // ---- C2: combine 8 G2 bufs -> publish my rank's state partial ----
        {
            const float* hb = hp + crow * 128 + cj;
            float4 s = *(const float4*)(hb);
            #pragma unroll
            for (int q = 1; q < 8; ++q)
                s = f4add(s, *(const float4*)(hb + q * 1024));
            __stcg((float4*)&g_pstate[t & 1][gcl][crank][crow][cj], s);
        }
        asm volatile("barrier.cluster.arrive.aligned;" ::: "memory");

        // ---- G1x(t+1) part A: rows 0-3, hides the barrier settle ----
        const float* xb = x2 + ((t + 1) & 1) * 1024 + wid * 16;
        if (t + 1 < T_STEPS)
            gemm16_rows(xb, w1x, hpxo, 0);

        asm volatile("barrier.cluster.wait.aligned;" ::: "memory");

        // ---- fold loads (valid after wait), hidden under G1x part B ----
        float4 p0 = __ldcg((const float4*)&g_pstate[t & 1][gcl][0][crow][cj]);
        float4 p1 = __ldcg((const float4*)&g_pstate[t & 1][gcl][1][crow][cj]);
        float4 p2 = __ldcg((const float4*)&g_pstate[t & 1][gcl][2][crow][cj]);
        float4 p3 = __ldcg((const float4*)&g_pstate[t & 1][gcl][3][crow][cj]);

        if (t + 1 < T_STEPS)
            gemm16_rows(xb, w1x, hpxo, 4);

        // ---- fold combine: a(t+1) = a(t) + sum(partials) + b2 ----
        {
            float4 acc = f4add(f4add(p0, p1), f4add(p2, p3));
            float4 av = *(float4*)(a_s + crow * DST + cj);
            av.x += acc.x + rb2.x;  av.y += acc.y + rb2.y;
            av.z += acc.z + rb2.z;  av.w += acc.w + rb2.w;
            *(float4*)(a_s + crow * DST + cj) = av;
        }
        // ---- stage x(t+2) into x2[t&1]; prefetch x(t+3) ----
        if (t + 2 < T_STEPS) {
            *(float4*)(x2 + (t & 1) * 1024 + crow * 128 + cj) = xr;
            if (t + 3 < T_STEPS)
                xr = *(const float4*)(xrow + (size_t)(t + 3) * DIN);
        }
        __syncthreads();   // B1
    }

    // ---- epilogue: a_s holds a(T); rank 0 writes out ----
    if (crank == 0) {
        float4 av = *(float4*)(a_s + crow * DST + cj);
        *(float4*)(out + (size_t)(rowbase + crow) * DST + cj) = av;
    }
}

extern "C" void kernel_launch(void* const* d_in, const int* in_sizes, int n_in,
                              void* d_out, int out_size) {
    const float* x  = (const float*)d_in[0];
    const float* a0 = (const float*)d_in[1];
    const float* W1 = (const float*)d_in[2];
    const float* b1 = (const float*)d_in[3];
    const float* W2 = (const float*)d_in[4];
    const float* b2 = (const float*)d_in[5];
    float* out = (float*)d_out;

    const size_t smem = SMEM_FLOATS * sizeof(float);   // 147456 B
    cudaFuncSetAttribute(rnn_kernel, cudaFuncAttributeMaxDynamicSharedMemorySize,
                         (int)smem);
    rnn_kernel<<<NCL * CSZ, NTHREADS, smem>>>(x, a0, W1, b1, W2, b2, out);
}